// round 11
// baseline (speedup 1.0000x reference)
#include <cuda_runtime.h>
#include <cuda_bf16.h>
#include <cuda/atomic>

#define NUM_P 41          // pred labels 0..40
#define NUM_C 26          // gt labels 0..25
#define BINS  (NUM_P * NUM_C)   // 1066
#define PAIRS (BINS / 2)        // 533
#define HIST_BLOCKS 1184        // 148 SMs * 8
#define HIST_THREADS 256

// Global scratch: bin pairs packed into u64 (lo = bin 2k, hi = bin 2k+1).
// Zero at module load; the winning block re-zeroes after use so graph replays
// start clean. Per-bin totals <= 2^24 so no carry crosses the 32-bit boundary.
__device__ unsigned long long g_counts64[PAIRS];
__device__ unsigned int g_ticket;

__global__ void __launch_bounds__(HIST_THREADS)
fused_kernel(const float4* __restrict__ pred4, const int4* __restrict__ gt4,
             const float* __restrict__ pred, const int* __restrict__ gt,
             int n4, int n, float* __restrict__ out) {
    __shared__ unsigned int h[BINS];
    for (int i = threadIdx.x; i < BINS; i += HIST_THREADS) h[i] = 0u;
    __syncthreads();

    const int stride = gridDim.x * HIST_THREADS;
    int i = blockIdx.x * HIST_THREADS + threadIdx.x;

    // Main loop: 2 float4 + 2 int4 loads in flight (MLP ~4), 1 ATOMS/voxel.
    for (; i + stride < n4; i += 2 * stride) {
        float4 p0 = pred4[i];
        int4   g0 = gt4[i];
        float4 p1 = pred4[i + stride];
        int4   g1 = gt4[i + stride];
        atomicAdd(&h[__float2int_rn(p0.x) * NUM_C + g0.x], 1u);
        atomicAdd(&h[__float2int_rn(p0.y) * NUM_C + g0.y], 1u);
        atomicAdd(&h[__float2int_rn(p0.z) * NUM_C + g0.z], 1u);
        atomicAdd(&h[__float2int_rn(p0.w) * NUM_C + g0.w], 1u);
        atomicAdd(&h[__float2int_rn(p1.x) * NUM_C + g1.x], 1u);
        atomicAdd(&h[__float2int_rn(p1.y) * NUM_C + g1.y], 1u);
        atomicAdd(&h[__float2int_rn(p1.z) * NUM_C + g1.z], 1u);
        atomicAdd(&h[__float2int_rn(p1.w) * NUM_C + g1.w], 1u);
    }
    for (; i < n4; i += stride) {
        float4 p = pred4[i];
        int4   g = gt4[i];
        atomicAdd(&h[__float2int_rn(p.x) * NUM_C + g.x], 1u);
        atomicAdd(&h[__float2int_rn(p.y) * NUM_C + g.y], 1u);
        atomicAdd(&h[__float2int_rn(p.z) * NUM_C + g.z], 1u);
        atomicAdd(&h[__float2int_rn(p.w) * NUM_C + g.w], 1u);
    }
    int tail_start = n4 * 4;
    for (int j = tail_start + blockIdx.x * HIST_THREADS + threadIdx.x; j < n;
         j += stride) {
        atomicAdd(&h[__float2int_rn(pred[j]) * NUM_C + gt[j]], 1u);
    }

    __syncthreads();
    // Flush: two bins per 64-bit relaxed global atomic.
    for (int k = threadIdx.x; k < PAIRS; k += HIST_THREADS) {
        unsigned int lo = h[2 * k];
        unsigned int hi = h[2 * k + 1];
        if (lo | hi)
            atomicAdd(&g_counts64[k],
                      (unsigned long long)lo | ((unsigned long long)hi << 32));
    }

    // Fence-free last-block election: release/acquire on the ticket itself.
    // Non-winners: the acq_rel RMW releases their flush atomics (no MEMBAR,
    // no L1 flush, no drain stall). Winner: same RMW acquires all of them.
    __shared__ unsigned int s_last;
    if (threadIdx.x == 0) {
        cuda::atomic_ref<unsigned int, cuda::thread_scope_device> tk(g_ticket);
        s_last = (tk.fetch_add(1u, cuda::memory_order_acq_rel)
                  == (unsigned)gridDim.x - 1u) ? 1u : 0u;
    }
    __syncthreads();   // broadcasts s_last; cta-scope fence covers the block
    if (!s_last) return;

    // ---- Winner-only finalize: flat sweep of 1066 bins into smem accums ----
    __shared__ unsigned int s_ps[NUM_P];
    __shared__ unsigned int s_gs[NUM_C];
    __shared__ unsigned int s_om[NUM_P];
    __shared__ unsigned int s_present;
    __shared__ float        s_dice[64];
    __shared__ float        s_fp[64];

    const int t = threadIdx.x;
    unsigned int* gc = (unsigned int*)g_counts64;   // bin k at gc[k]

    if (t < NUM_P) { s_ps[t] = 0u; s_om[t] = 0u; }
    if (t < NUM_C) s_gs[t] = 0u;
    __syncthreads();

    for (int k = t; k < BINS; k += HIST_THREADS) {
        cuda::atomic_ref<unsigned int, cuda::thread_scope_device> a(gc[k]);
        unsigned int v = a.load(cuda::memory_order_relaxed);  // L1-bypassing
        int p = k / NUM_C;
        int c = k - p * NUM_C;
        if (v) {
            atomicAdd(&s_ps[p], v);
            atomicAdd(&s_gs[c], v);
            if (c >= 1) atomicOr(&s_om[p], 1u << c);
        }
    }
    __syncthreads();

    if (t == 0) {
        unsigned int pm = 0u;
        for (int c = 1; c < NUM_C; c++)
            if (s_gs[c] > 0u) pm |= (1u << c);
        s_present = pm;
    }
    __syncthreads();
    const unsigned int pm = s_present;

    if (t < 64) {
        float contrib = 0.0f;
        if (t >= 1 && t < NUM_C && ((pm >> t) & 1u)) {
            float us = 0.0f;
            #pragma unroll
            for (int p = 0; p < NUM_P; p++)
                if ((s_om[p] >> t) & 1u) us += (float)s_ps[p];
            float gs = (float)s_gs[t];
            contrib = 2.0f * gs / (us + gs + 1.0f);
        }
        float fpc = 0.0f;
        if (t < NUM_P && s_ps[t] > 0u && (s_om[t] & pm) == 0u)
            fpc = 1.0f;
        s_dice[t] = contrib;
        s_fp[t]   = fpc;
    }
    __syncthreads();

    if (t == 0) {
        float lesion_dice = 0.0f, fp = 0.0f;
        for (int k = 0; k < 64; k++) { lesion_dice += s_dice[k]; fp += s_fp[k]; }
        float num_gt = (float)__popc(pm);
        out[0] = lesion_dice / (num_gt + fp);
    }
    __syncthreads();

    // Reset scratch for the next graph replay (kernel-boundary ordering makes
    // these plain stores visible to the next launch).
    for (int k = t; k < PAIRS; k += HIST_THREADS) g_counts64[k] = 0ull;
    if (t == 0) g_ticket = 0u;
}

extern "C" void kernel_launch(void* const* d_in, const int* in_sizes, int n_in,
                              void* d_out, int out_size) {
    const float* pred = (const float*)d_in[0];
    const int*   gt   = (const int*)d_in[1];
    float* out = (float*)d_out;
    const int n  = in_sizes[0];
    const int n4 = n >> 2;

    fused_kernel<<<HIST_BLOCKS, HIST_THREADS>>>(
        (const float4*)pred, (const int4*)gt, pred, gt, n4, n, out);
}

// round 12
// speedup vs baseline: 1.3556x; 1.3556x over previous
#include <cuda_runtime.h>
#include <cuda_bf16.h>

#define NUM_P 41          // pred labels 0..40
#define NUM_C 26          // gt labels 0..25
#define BINS  (NUM_P * NUM_C)   // 1066
#define PAIRS (BINS / 2)        // 533
#define HIST_BLOCKS 148         // one persistent block per SM
#define HIST_THREADS 1024       // 32 warps

// Global scratch: bin pairs packed into u64 (lo = bin 2k, hi = bin 2k+1).
// Zero at module load; finalize re-zeroes after use so graph replays start
// clean. Per-bin totals <= 2^24 so no carry crosses the 32-bit boundary.
__device__ unsigned long long g_counts64[PAIRS];

__global__ void __launch_bounds__(HIST_THREADS)
hist_kernel(const float4* __restrict__ pred4, const int4* __restrict__ gt4,
            const float* __restrict__ pred, const int* __restrict__ gt,
            int n4, int n) {
    __shared__ unsigned int h[BINS];
    for (int i = threadIdx.x; i < BINS; i += HIST_THREADS) h[i] = 0u;
    __syncthreads();

    const int stride = gridDim.x * HIST_THREADS;
    int i = blockIdx.x * HIST_THREADS + threadIdx.x;

    // Main loop: 2 float4 + 2 int4 loads in flight (MLP ~4), 1 ATOMS/voxel.
    for (; i + stride < n4; i += 2 * stride) {
        float4 p0 = pred4[i];
        int4   g0 = gt4[i];
        float4 p1 = pred4[i + stride];
        int4   g1 = gt4[i + stride];
        atomicAdd(&h[__float2int_rn(p0.x) * NUM_C + g0.x], 1u);
        atomicAdd(&h[__float2int_rn(p0.y) * NUM_C + g0.y], 1u);
        atomicAdd(&h[__float2int_rn(p0.z) * NUM_C + g0.z], 1u);
        atomicAdd(&h[__float2int_rn(p0.w) * NUM_C + g0.w], 1u);
        atomicAdd(&h[__float2int_rn(p1.x) * NUM_C + g1.x], 1u);
        atomicAdd(&h[__float2int_rn(p1.y) * NUM_C + g1.y], 1u);
        atomicAdd(&h[__float2int_rn(p1.z) * NUM_C + g1.z], 1u);
        atomicAdd(&h[__float2int_rn(p1.w) * NUM_C + g1.w], 1u);
    }
    for (; i < n4; i += stride) {
        float4 p = pred4[i];
        int4   g = gt4[i];
        atomicAdd(&h[__float2int_rn(p.x) * NUM_C + g.x], 1u);
        atomicAdd(&h[__float2int_rn(p.y) * NUM_C + g.y], 1u);
        atomicAdd(&h[__float2int_rn(p.z) * NUM_C + g.z], 1u);
        atomicAdd(&h[__float2int_rn(p.w) * NUM_C + g.w], 1u);
    }
    int tail_start = n4 * 4;
    for (int j = tail_start + blockIdx.x * HIST_THREADS + threadIdx.x; j < n;
         j += stride) {
        atomicAdd(&h[__float2int_rn(pred[j]) * NUM_C + gt[j]], 1u);
    }

    __syncthreads();
    // Flush: two bins per 64-bit global atomic; only 148 blocks total now,
    // so per-address contention and tail length are 8x smaller than before.
    for (int k = threadIdx.x; k < PAIRS; k += HIST_THREADS) {
        unsigned int lo = h[2 * k];
        unsigned int hi = h[2 * k + 1];
        if (lo | hi)
            atomicAdd(&g_counts64[k],
                      (unsigned long long)lo | ((unsigned long long)hi << 32));
    }
}

// Single block, 64 threads (measured-best): 41x26 reduction, then scratch reset.
__global__ void __launch_bounds__(64)
finalize_kernel(float* __restrict__ out) {
    __shared__ float        s_pred_sizes[NUM_P];
    __shared__ unsigned int s_omask[NUM_P];
    __shared__ float        s_gt_sizes[NUM_C];
    __shared__ unsigned int s_present;
    __shared__ float        s_dice[64];
    __shared__ float        s_fp[64];

    const int t = threadIdx.x;
    const unsigned int* gc = (const unsigned int*)g_counts64;  // bin k at gc[k]

    if (t < NUM_P) {
        float ps = 0.0f;
        unsigned int m = 0u;
        #pragma unroll
        for (int c = 0; c < NUM_C; c++) {
            unsigned int v = gc[t * NUM_C + c];
            ps += (float)v;
            if (c >= 1 && v) m |= (1u << c);
        }
        s_pred_sizes[t] = ps;
        s_omask[t] = m;
    }
    if (t < NUM_C) {
        float gs = 0.0f;
        #pragma unroll
        for (int p = 0; p < NUM_P; p++)
            gs += (float)gc[p * NUM_C + t];
        s_gt_sizes[t] = gs;
    }
    __syncthreads();

    if (t == 0) {
        unsigned int pm = 0u;
        for (int c = 1; c < NUM_C; c++)
            if (s_gt_sizes[c] > 0.0f) pm |= (1u << c);
        s_present = pm;
    }
    __syncthreads();
    const unsigned int pm = s_present;

    float contrib = 0.0f;
    if (t >= 1 && t < NUM_C && ((pm >> t) & 1u)) {
        float us = 0.0f;
        #pragma unroll
        for (int p = 0; p < NUM_P; p++)
            if ((s_omask[p] >> t) & 1u) us += s_pred_sizes[p];
        contrib = 2.0f * s_gt_sizes[t] / (us + s_gt_sizes[t] + 1.0f);
    }
    float fpc = 0.0f;
    if (t < NUM_P && s_pred_sizes[t] > 0.0f && (s_omask[t] & pm) == 0u)
        fpc = 1.0f;

    s_dice[t] = contrib;
    s_fp[t]   = fpc;
    __syncthreads();

    if (t == 0) {
        float lesion_dice = 0.0f, fp = 0.0f;
        for (int k = 0; k < 64; k++) { lesion_dice += s_dice[k]; fp += s_fp[k]; }
        float num_gt = (float)__popc(pm);
        out[0] = lesion_dice / (num_gt + fp);
    }
    __syncthreads();

    // Reset scratch for the next graph replay (deterministic across runs).
    for (int k = t; k < PAIRS; k += 64) g_counts64[k] = 0ull;
}

extern "C" void kernel_launch(void* const* d_in, const int* in_sizes, int n_in,
                              void* d_out, int out_size) {
    const float* pred = (const float*)d_in[0];
    const int*   gt   = (const int*)d_in[1];
    float* out = (float*)d_out;
    const int n  = in_sizes[0];
    const int n4 = n >> 2;

    hist_kernel<<<HIST_BLOCKS, HIST_THREADS>>>(
        (const float4*)pred, (const int4*)gt, pred, gt, n4, n);
    finalize_kernel<<<1, 64>>>(out);
}

// round 13
// speedup vs baseline: 1.3725x; 1.0124x over previous
#include <cuda_runtime.h>
#include <cuda_bf16.h>
#include <cuda/atomic>

#define NUM_P 41          // pred labels 0..40
#define NUM_C 26          // gt labels 0..25
#define BINS  (NUM_P * NUM_C)   // 1066
#define PAIRS (BINS / 2)        // 533
#define HIST_BLOCKS 148         // one block per SM
#define HIST_THREADS 1024       // 32 warps -> 1 block/SM regardless of regs

// Global scratch: bin pairs packed into u64 (lo = bin 2k, hi = bin 2k+1).
// Zero at module load; the winning block re-zeroes after use so graph replays
// start clean. Per-bin totals <= 2^24 so no carry crosses the 32-bit boundary.
__device__ unsigned long long g_counts64[PAIRS];
__device__ unsigned int g_ticket;

// Separate ABI allocation: keeps the epilogue's registers/codegen out of the
// hot mainloop. Runs once, on one block, after the ticket election.
__device__ __noinline__ void finalize_body(float* __restrict__ out) {
    __shared__ float        s_pred_sizes[NUM_P];
    __shared__ unsigned int s_omask[NUM_P];
    __shared__ float        s_gt_sizes[NUM_C];
    __shared__ unsigned int s_present;
    __shared__ float        s_dice[64];
    __shared__ float        s_fp[64];

    const int t = threadIdx.x;
    const unsigned int* gc = (const unsigned int*)g_counts64;  // bin k at gc[k]

    if (t < NUM_P) {
        float ps = 0.0f;
        unsigned int m = 0u;
        #pragma unroll
        for (int c = 0; c < NUM_C; c++) {
            unsigned int v = gc[t * NUM_C + c];
            ps += (float)v;
            if (c >= 1 && v) m |= (1u << c);
        }
        s_pred_sizes[t] = ps;
        s_omask[t] = m;
    }
    if (t < NUM_C) {
        float gs = 0.0f;
        #pragma unroll
        for (int p = 0; p < NUM_P; p++)
            gs += (float)gc[p * NUM_C + t];
        s_gt_sizes[t] = gs;
    }
    __syncthreads();

    if (t == 0) {
        unsigned int pm = 0u;
        for (int c = 1; c < NUM_C; c++)
            if (s_gt_sizes[c] > 0.0f) pm |= (1u << c);
        s_present = pm;
    }
    __syncthreads();
    const unsigned int pm = s_present;

    if (t < 64) {
        float contrib = 0.0f;
        if (t >= 1 && t < NUM_C && ((pm >> t) & 1u)) {
            float us = 0.0f;
            #pragma unroll
            for (int p = 0; p < NUM_P; p++)
                if ((s_omask[p] >> t) & 1u) us += s_pred_sizes[p];
            contrib = 2.0f * s_gt_sizes[t] / (us + s_gt_sizes[t] + 1.0f);
        }
        float fpc = 0.0f;
        if (t < NUM_P && s_pred_sizes[t] > 0.0f && (s_omask[t] & pm) == 0u)
            fpc = 1.0f;
        s_dice[t] = contrib;
        s_fp[t]   = fpc;
    }
    __syncthreads();

    if (t == 0) {
        float lesion_dice = 0.0f, fp = 0.0f;
        for (int k = 0; k < 64; k++) { lesion_dice += s_dice[k]; fp += s_fp[k]; }
        float num_gt = (float)__popc(pm);
        out[0] = lesion_dice / (num_gt + fp);
    }
    __syncthreads();

    // Reset scratch for the next graph replay (deterministic across runs).
    for (int k = t; k < PAIRS; k += HIST_THREADS) g_counts64[k] = 0ull;
    if (t == 0) g_ticket = 0u;
}

__global__ void __launch_bounds__(HIST_THREADS)
fused_kernel(const float4* __restrict__ pred4, const int4* __restrict__ gt4,
             const float* __restrict__ pred, const int* __restrict__ gt,
             int n4, int n, float* __restrict__ out) {
    __shared__ unsigned int h[BINS];
    for (int i = threadIdx.x; i < BINS; i += HIST_THREADS) h[i] = 0u;
    __syncthreads();

    const int stride = gridDim.x * HIST_THREADS;
    int i = blockIdx.x * HIST_THREADS + threadIdx.x;

    // Main loop: 2 float4 + 2 int4 loads in flight (MLP ~4), 1 ATOMS/voxel.
    for (; i + stride < n4; i += 2 * stride) {
        float4 p0 = pred4[i];
        int4   g0 = gt4[i];
        float4 p1 = pred4[i + stride];
        int4   g1 = gt4[i + stride];
        atomicAdd(&h[__float2int_rn(p0.x) * NUM_C + g0.x], 1u);
        atomicAdd(&h[__float2int_rn(p0.y) * NUM_C + g0.y], 1u);
        atomicAdd(&h[__float2int_rn(p0.z) * NUM_C + g0.z], 1u);
        atomicAdd(&h[__float2int_rn(p0.w) * NUM_C + g0.w], 1u);
        atomicAdd(&h[__float2int_rn(p1.x) * NUM_C + g1.x], 1u);
        atomicAdd(&h[__float2int_rn(p1.y) * NUM_C + g1.y], 1u);
        atomicAdd(&h[__float2int_rn(p1.z) * NUM_C + g1.z], 1u);
        atomicAdd(&h[__float2int_rn(p1.w) * NUM_C + g1.w], 1u);
    }
    for (; i < n4; i += stride) {
        float4 p = pred4[i];
        int4   g = gt4[i];
        atomicAdd(&h[__float2int_rn(p.x) * NUM_C + g.x], 1u);
        atomicAdd(&h[__float2int_rn(p.y) * NUM_C + g.y], 1u);
        atomicAdd(&h[__float2int_rn(p.z) * NUM_C + g.z], 1u);
        atomicAdd(&h[__float2int_rn(p.w) * NUM_C + g.w], 1u);
    }
    int tail_start = n4 * 4;
    for (int j = tail_start + blockIdx.x * HIST_THREADS + threadIdx.x; j < n;
         j += stride) {
        atomicAdd(&h[__float2int_rn(pred[j]) * NUM_C + gt[j]], 1u);
    }

    __syncthreads();
    // Flush: two bins per 64-bit global atomic; 148 blocks -> short tail.
    for (int k = threadIdx.x; k < PAIRS; k += HIST_THREADS) {
        unsigned int lo = h[2 * k];
        unsigned int hi = h[2 * k + 1];
        if (lo | hi)
            atomicAdd(&g_counts64[k],
                      (unsigned long long)lo | ((unsigned long long)hi << 32));
    }

    // Fence-free last-block election (release/acquire on the ticket itself).
    __shared__ unsigned int s_last;
    if (threadIdx.x == 0) {
        cuda::atomic_ref<unsigned int, cuda::thread_scope_device> tk(g_ticket);
        s_last = (tk.fetch_add(1u, cuda::memory_order_acq_rel)
                  == (unsigned)gridDim.x - 1u) ? 1u : 0u;
    }
    __syncthreads();
    if (!s_last) return;

    finalize_body(out);
}

extern "C" void kernel_launch(void* const* d_in, const int* in_sizes, int n_in,
                              void* d_out, int out_size) {
    const float* pred = (const float*)d_in[0];
    const int*   gt   = (const int*)d_in[1];
    float* out = (float*)d_out;
    const int n  = in_sizes[0];
    const int n4 = n >> 2;

    fused_kernel<<<HIST_BLOCKS, HIST_THREADS>>>(
        (const float4*)pred, (const int4*)gt, pred, gt, n4, n, out);
}